// round 9
// baseline (speedup 1.0000x reference)
#include <cuda_runtime.h>
#include <cstddef>

// ===========================================================================
// WorldModel RSSM: persistent single-kernel implementation.
// S=32 C=32 D=4096 H=1024 A=6 B=16 T=64 TOK=4096, out feats [16,64,5120]
// ===========================================================================

#define NBLK 148
#define TPB  1024
#define GPB  8                 // 128-thread groups per block
#define NG   (NBLK * GPB)      // 1184 groups

#define CH_P1 64               // posterior layer1 K-chunks (K=8192, Kc=128)
#define CH_Q1 32               // prior layer1 K-chunks     (K=4096, Kc=128)
#define CH_L  32               // layers 2/3 K-chunks       (K=1024, Kc=32)
#define CH_ZC 16               // z/cand GEMM K-chunks      (K=5120, Kc=320)

// ---------------------------------------------------------------------------
// Device scratch (static — no allocations)
// ---------------------------------------------------------------------------
__device__ float g_deter[16 * 4096];
__device__ float g_gx[16 * 1024];
__device__ float g_hqA[16 * 1024];
__device__ float g_hqB[16 * 1024];
__device__ float g_hpA[16 * 1024];
__device__ float g_hpB[16 * 1024];
__device__ float g_partQ[CH_Q1 * 16 * 1024];
__device__ float g_partP[CH_P1 * 16 * 1024];
__device__ float g_partZ[CH_ZC * 16 * 4096];
__device__ float g_partC[CH_ZC * 16 * 4096];
__device__ int   g_idx[16 * 32];
__device__ unsigned g_count;
__device__ unsigned g_gen;

// ---------------------------------------------------------------------------
// Packed f32x2 FMA
// ---------------------------------------------------------------------------
__device__ __forceinline__ float2 ffma2(float2 a, float2 b, float2 c) {
    union U { float2 f; unsigned long long u; };
    U ua, ub, uc, ud;
    ua.f = a; ub.f = b; uc.f = c;
    asm("fma.rn.f32x2 %0, %1, %2, %3;"
        : "=l"(ud.u) : "l"(ua.u), "l"(ub.u), "l"(uc.u));
    return ud.f;
}

// ---------------------------------------------------------------------------
// Grid-wide barrier (all NBLK blocks co-resident)
// ---------------------------------------------------------------------------
__device__ __forceinline__ void gbar() {
    __syncthreads();
    if (threadIdx.x == 0) {
        volatile unsigned* vg = &g_gen;
        unsigned gen = *vg;
        __threadfence();
        if (atomicAdd(&g_count, 1u) == NBLK - 1) {
            g_count = 0;
            __threadfence();
            *vg = gen + 1;
        } else {
            while (*vg == gen) { __nanosleep(64); }
        }
        __threadfence();
    }
    __syncthreads();
}

// ---------------------------------------------------------------------------
// Block-wide sum over 1024 threads
// ---------------------------------------------------------------------------
__device__ __forceinline__ float blockReduceSum(float v, float* sred) {
    int lane = threadIdx.x & 31, wid = threadIdx.x >> 5;
#pragma unroll
    for (int o = 16; o; o >>= 1) v += __shfl_xor_sync(0xffffffffu, v, o);
    __syncthreads();
    if (lane == 0) sred[wid] = v;
    __syncthreads();
    if (wid == 0) {
        float t = sred[lane];
#pragma unroll
        for (int o = 16; o; o >>= 1) t += __shfl_xor_sync(0xffffffffu, t, o);
        if (lane == 0) sred[0] = t;
    }
    __syncthreads();
    return sred[0];
}

// ---------------------------------------------------------------------------
// Input descriptor: value(m,k) = k<KA ? A[m*strideA + offA + k]
//                               : B[m*4096 + (k-KA)]
// ---------------------------------------------------------------------------
struct InDesc {
    const float* A; int strideA; int offA; int KA; const float* B;
};

// ---------------------------------------------------------------------------
// One GEMM tile: 128 cols (col = c0+gtid), Kc rows, 16 batch rows.
// Partials to part[(chunkIdx*16 + m)*N + col].
// ---------------------------------------------------------------------------
__device__ __forceinline__ void gemm_group(
    InDesc in, const float* __restrict__ W, int N,
    int c0, int k0, int Kc, float* __restrict__ part, int chunkIdx,
    float* sIn, int gtid, int barId)
{
    float2 acc[8];
#pragma unroll
    for (int i = 0; i < 8; i++) acc[i] = make_float2(0.f, 0.f);
    int col = c0 + gtid;

    for (int kb = 0; kb < Kc; kb += 32) {
        int kbase = k0 + kb;
#pragma unroll
        for (int i = 0; i < 4; i++) {
            int e = gtid + (i << 7);
            int kk = e >> 4, m = e & 15;
            int k = kbase + kk;
            float v = (k < in.KA) ? in.A[m * in.strideA + in.offA + k]
                                  : in.B[m * 4096 + (k - in.KA)];
            sIn[kk * 16 + m] = v;
        }
        asm volatile("bar.sync %0, %1;" :: "r"(barId), "r"(128) : "memory");
#pragma unroll 8
        for (int kk = 0; kk < 32; kk++) {
            float w = W[(size_t)(kbase + kk) * N + col];
            const float4* r4 = (const float4*)(sIn + kk * 16);
            float4 p0 = r4[0], p1 = r4[1], p2 = r4[2], p3 = r4[3];
            float2 ww = make_float2(w, w);
            acc[0] = ffma2(make_float2(p0.x, p0.y), ww, acc[0]);
            acc[1] = ffma2(make_float2(p0.z, p0.w), ww, acc[1]);
            acc[2] = ffma2(make_float2(p1.x, p1.y), ww, acc[2]);
            acc[3] = ffma2(make_float2(p1.z, p1.w), ww, acc[3]);
            acc[4] = ffma2(make_float2(p2.x, p2.y), ww, acc[4]);
            acc[5] = ffma2(make_float2(p2.z, p2.w), ww, acc[5]);
            acc[6] = ffma2(make_float2(p3.x, p3.y), ww, acc[6]);
            acc[7] = ffma2(make_float2(p3.z, p3.w), ww, acc[7]);
        }
        asm volatile("bar.sync %0, %1;" :: "r"(barId), "r"(128) : "memory");
    }

    int base = chunkIdx * 16;
#pragma unroll
    for (int rp = 0; rp < 8; rp++) {
        part[(size_t)(base + 2 * rp) * N + col]     = acc[rp].x;
        part[(size_t)(base + 2 * rp + 1) * N + col] = acc[rp].y;
    }
}

// ---------------------------------------------------------------------------
// Phase: fused layer-1 GEMMs (prior q: K=4096; posterior p for t+1: K=8192)
// ---------------------------------------------------------------------------
__device__ void phase_g1(bool doq, bool dop, int tp, const float* tokens,
                         const float* qW1, const float* pW1,
                         float* sMy, int gtid, int gid2, int barId)
{
    int qT = doq ? (8 * CH_Q1) : 0;                 // 256 tiles
    int total = qT + (dop ? (8 * CH_P1) : 0);       // +512 tiles
    for (int t = gid2; t < total; t += NG) {
        if (t < qT) {
            int ch = t >> 3, ct = t & 7;
            InDesc in = { g_deter, 4096, 0, 4096, (const float*)0 };
            gemm_group(in, qW1, 1024, ct * 128, ch * 128, 128,
                       g_partQ, ch, sMy, gtid, barId);
        } else {
            int u = t - qT;
            int ch = u >> 3, ct = u & 7;
            InDesc in = { tokens, 64 * 4096, tp * 4096, 4096, g_deter };
            gemm_group(in, pW1, 1024, ct * 128, ch * 128, 128,
                       g_partP, ch, sMy, gtid, barId);
        }
    }
}

// ---------------------------------------------------------------------------
// Phase: fused layer-2/3 GEMMs (K=1024 each side)
// ---------------------------------------------------------------------------
__device__ void phase_g23(bool doq, bool dop,
                          const float* Wq, const float* Wp,
                          const float* inq, const float* inp,
                          float* sMy, int gtid, int gid2, int barId)
{
    int qT = doq ? (8 * CH_L) : 0;                  // 256
    int total = qT + (dop ? (8 * CH_L) : 0);
    for (int t = gid2; t < total; t += NG) {
        bool isq = t < qT;
        int u = isq ? t : (t - qT);
        int ch = u >> 3, ct = u & 7;
        InDesc in = { isq ? inq : inp, 1024, 0, 1024, (const float*)0 };
        gemm_group(in, isq ? Wq : Wp, 1024, ct * 128, ch * 32, 32,
                   isq ? g_partQ : g_partP, ch, sMy, gtid, barId);
    }
}

// ---------------------------------------------------------------------------
// Phase: z/cand GEMM. in = concat(gx[16,1024], deter[16,4096]), K=5120,
// N=4096 per matrix. 1024 tiles.
// ---------------------------------------------------------------------------
__device__ void phase_zc(const float* Wz, const float* Wc,
                         float* sMy, int gtid, int gid2, int barId)
{
    const int total = 2 * 32 * CH_ZC;               // 1024
    for (int t = gid2; t < total; t += NG) {
        bool isZ = t < 512;
        int u = t & 511;
        int ct = u & 31, ch = u >> 5;               // 32 coltiles, 16 chunks
        InDesc in = { g_gx, 1024, 0, 1024, g_deter };
        gemm_group(in, isZ ? Wz : Wc, 4096, ct * 128, ch * 320, 320,
                   isZ ? g_partZ : g_partC, ch, sMy, gtid, barId);
    }
}

// ---------------------------------------------------------------------------
// Phase: reduce partials + bias + LayerNorm + SiLU. Blocks 0..15 = q rows,
// 16..31 = p rows.
// ---------------------------------------------------------------------------
__device__ void phase_ln(bool doq, bool dop,
                         const float* qb, const float* qg, const float* qB,
                         const float* pb, const float* pg, const float* pB,
                         int chq, int chp, float* outq, float* outp,
                         float* sred)
{
    int b = blockIdx.x;
    if (b >= 32) return;
    bool isq = b < 16;
    if (isq ? !doq : !dop) return;
    int r = b & 15;
    const float* part = isq ? g_partQ : g_partP;
    int chunks = isq ? chq : chp;
    int col = threadIdx.x;

    float v = (isq ? qb : pb)[col];
#pragma unroll 8
    for (int ch = 0; ch < chunks; ch++)
        v += part[(size_t)(ch * 16 + r) * 1024 + col];

    float mean = blockReduceSum(v, sred) * (1.0f / 1024.0f);
    float d = v - mean;
    float var = blockReduceSum(d * d, sred) * (1.0f / 1024.0f);
    float rstd = rsqrtf(var + 1e-5f);
    float x = d * rstd * (isq ? qg : pg)[col] + (isq ? qB : pB)[col];
    float* outh = isq ? outq : outp;
    outh[r * 1024 + col] = x / (1.0f + expf(-x));
}

// ---------------------------------------------------------------------------
// Phase: logits reduce + unimix softmax + gumbel-max. Blocks 0..15 = prior(t)
// -> feat; 16..31 = posterior(tp) -> g_idx. One warp per s.
// ---------------------------------------------------------------------------
__device__ void phase_sample(bool doq, bool dop, int t, int tp,
                             const float* qbo, const float* pbo,
                             const float* gprior, const float* gpost,
                             float* out)
{
    int b = blockIdx.x;
    if (b >= 32) return;
    bool isq = b < 16;
    if (isq ? !doq : !dop) return;
    int r = b & 15;
    int s = threadIdx.x >> 5, lane = threadIdx.x & 31;
    int col = s * 32 + lane;

    const float* part = isq ? g_partQ : g_partP;
    float logit = (isq ? qbo : pbo)[col];
#pragma unroll 8
    for (int ch = 0; ch < CH_L; ch++)
        logit += part[(size_t)(ch * 16 + r) * 1024 + col];

    float mx = logit;
#pragma unroll
    for (int o = 16; o; o >>= 1) mx = fmaxf(mx, __shfl_xor_sync(0xffffffffu, mx, o));
    float e = expf(logit - mx);
    float se = e;
#pragma unroll
    for (int o = 16; o; o >>= 1) se += __shfl_xor_sync(0xffffffffu, se, o);
    float p = 0.99f * (e / se) + (0.01f / 32.0f);

    int tt = isq ? t : tp;
    const float* gum = isq ? gprior : gpost;
    float score = logf(p) + gum[(size_t)((tt * 16 + r) * 32 + s) * 32 + lane];

    float bs = score; int bi = lane;
#pragma unroll
    for (int o = 16; o; o >>= 1) {
        float os = __shfl_xor_sync(0xffffffffu, bs, o);
        int   oi = __shfl_xor_sync(0xffffffffu, bi, o);
        if (os > bs || (os == bs && oi < bi)) { bs = os; bi = oi; }
    }

    if (isq) {
        // straight-through forward = exact one-hot
        out[((size_t)r * 64 + t) * 5120 + 4096 + col] = (lane == bi) ? 1.0f : 0.0f;
    } else if (lane == bi) {
        g_idx[r * 32 + s] = bi;
    }
}

// ---------------------------------------------------------------------------
// Phase: GRU input x = silu(ln(gather(gW, idx) + act @ gW[1024:1030] + gb)).
// Blocks 0..15, one per batch row.
// ---------------------------------------------------------------------------
__device__ void phase_grux(int t, const float* actions,
                           const float* gW, const float* gb,
                           const float* gg, const float* gB,
                           int* sIdx, float* sAct, float* sred)
{
    int b = blockIdx.x;
    if (b >= 16) return;
    int tid = threadIdx.x;
    if (tid < 32) sIdx[tid] = g_idx[b * 32 + tid];
    if (tid >= 32 && tid < 38) sAct[tid - 32] = actions[((size_t)b * 64 + t) * 6 + (tid - 32)];
    __syncthreads();

    int col = tid;
    float v = gb[col];
#pragma unroll
    for (int s = 0; s < 32; s++)
        v += gW[(size_t)(s * 32 + sIdx[s]) * 1024 + col];
#pragma unroll
    for (int j = 0; j < 6; j++)
        v += sAct[j] * gW[(size_t)(1024 + j) * 1024 + col];

    float mean = blockReduceSum(v, sred) * (1.0f / 1024.0f);
    float d = v - mean;
    float var = blockReduceSum(d * d, sred) * (1.0f / 1024.0f);
    float rstd = rsqrtf(var + 1e-5f);
    float x = d * rstd * gg[col] + gB[col];
    g_gx[b * 1024 + col] = x / (1.0f + expf(-x));
}

// ---------------------------------------------------------------------------
// Phase: gate — reduce z/cand partials, update deter, write feat deter slice.
// Blocks 0..15, 4 cols/thread via float4.
// ---------------------------------------------------------------------------
__device__ void phase_gate(int t, const float* gbz, const float* gbc,
                           float* out)
{
    int b = blockIdx.x;
    if (b >= 16) return;
    int c4 = threadIdx.x;                       // 1024 float4 slots = 4096 cols
    const float4* bz4 = (const float4*)gbz;
    const float4* bc4 = (const float4*)gbc;
    const float4* pz4 = (const float4*)g_partZ;
    const float4* pc4 = (const float4*)g_partC;
    float4 zp = bz4[c4], cp = bc4[c4];
#pragma unroll
    for (int ch = 0; ch < CH_ZC; ch++) {
        float4 a = pz4[(size_t)(ch * 16 + b) * 1024 + c4];
        float4 c = pc4[(size_t)(ch * 16 + b) * 1024 + c4];
        zp.x += a.x; zp.y += a.y; zp.z += a.z; zp.w += a.w;
        cp.x += c.x; cp.y += c.y; cp.z += c.z; cp.w += c.w;
    }
    float4* dt4 = (float4*)g_deter;
    float4 dv = dt4[b * 1024 + c4];
    float4 dn;
    {
        float z, cd;
        z = 1.f / (1.f + expf(-zp.x)); cd = tanhf(cp.x); dn.x = (1.f - z) * dv.x + z * cd;
        z = 1.f / (1.f + expf(-zp.y)); cd = tanhf(cp.y); dn.y = (1.f - z) * dv.y + z * cd;
        z = 1.f / (1.f + expf(-zp.z)); cd = tanhf(cp.z); dn.z = (1.f - z) * dv.z + z * cd;
        z = 1.f / (1.f + expf(-zp.w)); cd = tanhf(cp.w); dn.w = (1.f - z) * dv.w + z * cd;
    }
    dt4[b * 1024 + c4] = dn;
    float4* o4 = (float4*)(out + ((size_t)b * 64 + t) * 5120);
    o4[c4] = dn;
}

// ---------------------------------------------------------------------------
// The persistent kernel
// ---------------------------------------------------------------------------
__global__ void __launch_bounds__(TPB, 1)
wm_kernel(const float* tokens, const float* actions,
          const float* gpost, const float* gprior,
          const float* pW1, const float* pb1, const float* pg1, const float* pB1,
          const float* pW2, const float* pb2, const float* pg2, const float* pB2,
          const float* pWo, const float* pbo,
          const float* qW1, const float* qb1, const float* qg1, const float* qB1,
          const float* qW2, const float* qb2, const float* qg2, const float* qB2,
          const float* qWo, const float* qbo,
          const float* gW, const float* gb, const float* gg, const float* gB,
          const float* gWz, const float* gbz, const float* gWc, const float* gbc,
          float* out)
{
    __shared__ float4 sPool4[GPB * 128];        // 8 groups x 512 floats staging
    __shared__ float  sRed[32];
    __shared__ int    sIdx[32];
    __shared__ float  sAct[6];

    int tid = threadIdx.x;
    int g = tid >> 7, gtid = tid & 127;
    int gid2 = g * NBLK + blockIdx.x;           // spread tiles across SMs
    float* sMy = (float*)(sPool4 + g * 128);
    int barId = g + 1;

    // zero deter
    {
        int i = blockIdx.x * TPB + tid;
        if (i < 16 * 4096) g_deter[i] = 0.0f;
    }
    gbar();

    // initial posterior(t=0) (p-side only)
    phase_g1(false, true, 0, tokens, qW1, pW1, sMy, gtid, gid2, barId);      gbar();
    phase_ln(false, true, qb1, qg1, qB1, pb1, pg1, pB1, CH_Q1, CH_P1,
             g_hqA, g_hpA, sRed);                                            gbar();
    phase_g23(false, true, qW2, pW2, g_hqA, g_hpA, sMy, gtid, gid2, barId);  gbar();
    phase_ln(false, true, qb2, qg2, qB2, pb2, pg2, pB2, CH_L, CH_L,
             g_hqB, g_hpB, sRed);                                            gbar();
    phase_g23(false, true, qWo, pWo, g_hqB, g_hpB, sMy, gtid, gid2, barId);  gbar();
    phase_sample(false, true, 0, 0, qbo, pbo, gprior, gpost, out);           gbar();

    for (int t = 0; t < 64; t++) {
        // MiniGRU
        phase_grux(t, actions, gW, gb, gg, gB, sIdx, sAct, sRed);            gbar();
        phase_zc(gWz, gWc, sMy, gtid, gid2, barId);                          gbar();
        phase_gate(t, gbz, gbc, out);                                        gbar();

        // prior(t) fused with posterior(t+1)
        bool dop = (t < 63);
        phase_g1(true, dop, t + 1, tokens, qW1, pW1, sMy, gtid, gid2, barId); gbar();
        phase_ln(true, dop, qb1, qg1, qB1, pb1, pg1, pB1, CH_Q1, CH_P1,
                 g_hqA, g_hpA, sRed);                                         gbar();
        phase_g23(true, dop, qW2, pW2, g_hqA, g_hpA, sMy, gtid, gid2, barId); gbar();
        phase_ln(true, dop, qb2, qg2, qB2, pb2, pg2, pB2, CH_L, CH_L,
                 g_hqB, g_hpB, sRed);                                         gbar();
        phase_g23(true, dop, qWo, pWo, g_hqB, g_hpB, sMy, gtid, gid2, barId); gbar();
        phase_sample(true, dop, t, t + 1, qbo, pbo, gprior, gpost, out);      gbar();
    }
}

// ---------------------------------------------------------------------------
// Host launcher — single kernel launch, single graph node.
// ---------------------------------------------------------------------------
extern "C" void kernel_launch(void* const* d_in, const int* in_sizes, int n_in,
                              void* d_out, int out_size) {
    const float* tokens  = (const float*)d_in[0];
    const float* actions = (const float*)d_in[1];
    const float* gpost   = (const float*)d_in[2];
    const float* gprior  = (const float*)d_in[3];
    const float* pW1 = (const float*)d_in[4];  const float* pb1 = (const float*)d_in[5];
    const float* pg1 = (const float*)d_in[6];  const float* pB1 = (const float*)d_in[7];
    const float* pW2 = (const float*)d_in[8];  const float* pb2 = (const float*)d_in[9];
    const float* pg2 = (const float*)d_in[10]; const float* pB2 = (const float*)d_in[11];
    const float* pWo = (const float*)d_in[12]; const float* pbo = (const float*)d_in[13];
    const float* qW1 = (const float*)d_in[14]; const float* qb1 = (const float*)d_in[15];
    const float* qg1 = (const float*)d_in[16]; const float* qB1 = (const float*)d_in[17];
    const float* qW2 = (const float*)d_in[18]; const float* qb2 = (const float*)d_in[19];
    const float* qg2 = (const float*)d_in[20]; const float* qB2 = (const float*)d_in[21];
    const float* qWo = (const float*)d_in[22]; const float* qbo = (const float*)d_in[23];
    const float* gW  = (const float*)d_in[24]; const float* gb  = (const float*)d_in[25];
    const float* gg  = (const float*)d_in[26]; const float* gB  = (const float*)d_in[27];
    const float* gWz = (const float*)d_in[28]; const float* gbz = (const float*)d_in[29];
    const float* gWc = (const float*)d_in[30]; const float* gbc = (const float*)d_in[31];

    wm_kernel<<<NBLK, TPB>>>(tokens, actions, gpost, gprior,
                             pW1, pb1, pg1, pB1, pW2, pb2, pg2, pB2, pWo, pbo,
                             qW1, qb1, qg1, qB1, qW2, qb2, qg2, qB2, qWo, qbo,
                             gW, gb, gg, gB, gWz, gbz, gWc, gbc,
                             (float*)d_out);
}

// round 10
// speedup vs baseline: 1.0812x; 1.0812x over previous
#include <cuda_runtime.h>
#include <cstddef>

// ===========================================================================
// WorldModel RSSM persistent kernel, vectorized GEMM tiles.
// S=32 C=32 D=4096 H=1024 A=6 B=16 T=64 TOK=4096, out feats [16,64,5120]
// ===========================================================================

#define NBLK 148
#define TPB  1024
#define GPB  4                  // 256-thread groups per block
#define NG   (NBLK * GPB)       // 592 groups

#define CH_Q1 64                // prior layer1:  K=4096, Kc=64
#define CH_P1 128               // post  layer1:  K=8192, Kc=64
#define CH_L  32                // layers 2/3:    K=1024, Kc=32
#define CH_ZC 32                // z/cand:        K=5120, Kc=160

// ---------------------------------------------------------------------------
// Device scratch
// ---------------------------------------------------------------------------
__device__ float g_deter[16 * 4096];
__device__ float g_gx[16 * 1024];
__device__ float g_hqA[16 * 1024];
__device__ float g_hqB[16 * 1024];
__device__ float g_hpA[16 * 1024];
__device__ float g_hpB[16 * 1024];
__device__ float g_partQ[CH_Q1 * 16 * 1024];
__device__ float g_partP[CH_P1 * 16 * 1024];
__device__ float g_partZ[CH_ZC * 16 * 4096];
__device__ float g_partC[CH_ZC * 16 * 4096];
__device__ int   g_idx[16 * 32];
__device__ unsigned g_count;
__device__ unsigned g_gen;

// ---------------------------------------------------------------------------
__device__ __forceinline__ float2 ffma2(float2 a, float2 b, float2 c) {
    union U { float2 f; unsigned long long u; };
    U ua, ub, uc, ud;
    ua.f = a; ub.f = b; uc.f = c;
    asm("fma.rn.f32x2 %0, %1, %2, %3;"
        : "=l"(ud.u) : "l"(ua.u), "l"(ub.u), "l"(uc.u));
    return ud.f;
}

__device__ __forceinline__ void gbar() {
    __syncthreads();
    if (threadIdx.x == 0) {
        volatile unsigned* vg = &g_gen;
        unsigned gen = *vg;
        __threadfence();
        if (atomicAdd(&g_count, 1u) == NBLK - 1) {
            g_count = 0;
            __threadfence();
            *vg = gen + 1;
        } else {
            while (*vg == gen) { __nanosleep(64); }
        }
        __threadfence();
    }
    __syncthreads();
}

__device__ __forceinline__ float blockReduceSum(float v, float* sred) {
    int lane = threadIdx.x & 31, wid = threadIdx.x >> 5;
#pragma unroll
    for (int o = 16; o; o >>= 1) v += __shfl_xor_sync(0xffffffffu, v, o);
    __syncthreads();
    if (lane == 0) sred[wid] = v;
    __syncthreads();
    if (wid == 0) {
        float t = sred[lane];
#pragma unroll
        for (int o = 16; o; o >>= 1) t += __shfl_xor_sync(0xffffffffu, t, o);
        if (lane == 0) sred[0] = t;
    }
    __syncthreads();
    return sred[0];
}

struct InDesc { const float* A; int strideA; int offA; int KA; const float* B; };

// ---------------------------------------------------------------------------
// GEMM tile, R rows per thread (R = 8 or 4), 4 cols per thread (LDG.128).
// Group = 256 threads covering 1024 columns. Cols = c4base*4 + gtid*4 .. +3.
// Rows = rowbase .. rowbase+R-1 of the 16 batch rows.
// Partials: part4[(chunkIdx*16 + row)*N4 + col4]
// ---------------------------------------------------------------------------
template <int R>
__device__ __forceinline__ void gemm_g(
    InDesc in, const float4* __restrict__ W4, int N4,
    int c4base, int rowbase, int k0, int Kc,
    float4* __restrict__ part4, int chunkIdx,
    float* sIn, int gtid, int barId)
{
    float2 acc[R / 2][4];
#pragma unroll
    for (int rp = 0; rp < R / 2; rp++)
#pragma unroll
        for (int c = 0; c < 4; c++) acc[rp][c] = make_float2(0.f, 0.f);

    int col4 = c4base + gtid;
    int kks = gtid & 31, rs = gtid >> 5;     // staging: coalesced k, row-major

    for (int kb = 0; kb < Kc; kb += 32) {
        int kbase = k0 + kb;
        if (rs < R) {
            int k = kbase + kks, row = rowbase + rs;
            float v = (k < in.KA) ? in.A[(size_t)row * in.strideA + in.offA + k]
                                  : in.B[(size_t)row * 4096 + (k - in.KA)];
            sIn[kks * R + rs] = v;
        }
        asm volatile("bar.sync %0, %1;" :: "r"(barId), "r"(256) : "memory");

        const float4* Wp = W4 + (size_t)kbase * N4 + col4;
#pragma unroll 4
        for (int kk = 0; kk < 32; kk++) {
            float4 w = Wp[(size_t)kk * N4];
            const float2* a2 = (const float2*)(sIn + kk * R);
            float2 wx = make_float2(w.x, w.x), wy = make_float2(w.y, w.y);
            float2 wz = make_float2(w.z, w.z), ww = make_float2(w.w, w.w);
#pragma unroll
            for (int rp = 0; rp < R / 2; rp++) {
                float2 a = a2[rp];
                acc[rp][0] = ffma2(a, wx, acc[rp][0]);
                acc[rp][1] = ffma2(a, wy, acc[rp][1]);
                acc[rp][2] = ffma2(a, wz, acc[rp][2]);
                acc[rp][3] = ffma2(a, ww, acc[rp][3]);
            }
        }
        asm volatile("bar.sync %0, %1;" :: "r"(barId), "r"(256) : "memory");
    }

#pragma unroll
    for (int r = 0; r < R; r++) {
        int rp = r >> 1;
        float4 o;
        if (r & 1) o = make_float4(acc[rp][0].y, acc[rp][1].y, acc[rp][2].y, acc[rp][3].y);
        else       o = make_float4(acc[rp][0].x, acc[rp][1].x, acc[rp][2].x, acc[rp][3].x);
        part4[(size_t)(chunkIdx * 16 + rowbase + r) * N4 + col4] = o;
    }
}

// ---------------------------------------------------------------------------
// Phase: fused layer-1 GEMMs. q: deter@qW1 (K=4096). p: [tok(tp),deter]@pW1.
// Tiles: q = CH_Q1*2 (rowtiles), p = CH_P1*2.
// ---------------------------------------------------------------------------
__device__ void phase_g1(bool doq, bool dop, int tp, const float* tokens,
                         const float4* qW1, const float4* pW1,
                         float* sMy, int gtid, int gid2, int barId)
{
    int qT = doq ? (2 * CH_Q1) : 0;
    int total = qT + (dop ? (2 * CH_P1) : 0);
    for (int t = gid2; t < total; t += NG) {
        if (t < qT) {
            int ch = t >> 1, rh = t & 1;
            InDesc in = { g_deter, 4096, 0, 4096, g_deter };
            gemm_g<8>(in, qW1, 256, 0, rh * 8, ch * 64, 64,
                      (float4*)g_partQ, ch, sMy, gtid, barId);
        } else {
            int u = t - qT;
            int ch = u >> 1, rh = u & 1;
            InDesc in = { tokens, 64 * 4096, tp * 4096, 4096, g_deter };
            gemm_g<8>(in, pW1, 256, 0, rh * 8, ch * 64, 64,
                      (float4*)g_partP, ch, sMy, gtid, barId);
        }
    }
}

// ---------------------------------------------------------------------------
// Phase: fused layer-2/3 GEMMs (K=1024). 4-rows/thread tiles: 128 per side.
// ---------------------------------------------------------------------------
__device__ void phase_g23(bool doq, bool dop,
                          const float4* Wq, const float4* Wp,
                          const float* inq, const float* inp,
                          float* sMy, int gtid, int gid2, int barId)
{
    int qT = doq ? (4 * CH_L) : 0;
    int total = qT + (dop ? (4 * CH_L) : 0);
    for (int t = gid2; t < total; t += NG) {
        bool isq = t < qT;
        int u = isq ? t : (t - qT);
        int ch = u >> 2, rh = u & 3;
        InDesc in = { isq ? inq : inp, 1024, 0, 1024, isq ? inq : inp };
        gemm_g<4>(in, isq ? Wq : Wp, 256, 0, rh * 4, ch * 32, 32,
                  (float4*)(isq ? g_partQ : g_partP), ch, sMy, gtid, barId);
    }
}

// ---------------------------------------------------------------------------
// Phase: z/cand GEMM. in = [gx, deter] (K=5120), N=4096 each. 512 tiles.
// ---------------------------------------------------------------------------
__device__ void phase_zc(const float4* Wz, const float4* Wc,
                         float* sMy, int gtid, int gid2, int barId)
{
    const int total = 2 * 8 * CH_ZC;            // 512
    for (int t = gid2; t < total; t += NG) {
        bool isZ = t < 256;
        int u = t & 255;
        int ch = u >> 3, sub = u & 7;
        int ct = sub >> 1, rh = sub & 1;
        InDesc in = { g_gx, 1024, 0, 1024, g_deter };
        gemm_g<8>(in, isZ ? Wz : Wc, 1024, ct * 256, rh * 8, ch * 160, 160,
                  (float4*)(isZ ? g_partZ : g_partC), ch, sMy, gtid, barId);
    }
}

// ---------------------------------------------------------------------------
// Phase: reduce partials + bias + LN + SiLU. Blocks 0..15 q, 16..31 p.
// float4 cols, 4-way chunk split combined in smem.
// ---------------------------------------------------------------------------
__device__ void phase_ln(bool doq, bool dop,
                         const float* qb, const float* qg, const float* qB,
                         const float* pb, const float* pg, const float* pB,
                         int chq, int chp, float* outq, float* outp,
                         float4* sLN, float* sred)
{
    int b = blockIdx.x;
    bool active = (b < 32);
    bool isq = b < 16;
    if (active && (isq ? !doq : !dop)) active = false;

    int s = threadIdx.x & 255, qd = threadIdx.x >> 8;
    float4 v = make_float4(0.f, 0.f, 0.f, 0.f);
    if (active) {
        int r = b & 15;
        const float4* part4 = (const float4*)(isq ? g_partQ : g_partP);
        int chunks = isq ? chq : chp;
        for (int ch = qd; ch < chunks; ch += 4) {
            float4 a = part4[(size_t)(ch * 16 + r) * 256 + s];
            v.x += a.x; v.y += a.y; v.z += a.z; v.w += a.w;
        }
    }
    sLN[qd * 256 + s] = v;
    __syncthreads();

    float4 tot = make_float4(0.f, 0.f, 0.f, 0.f);
    float partial = 0.f;
    if (active && qd == 0) {
        float4 a0 = sLN[s], a1 = sLN[256 + s], a2 = sLN[512 + s], a3 = sLN[768 + s];
        const float4* bias4 = (const float4*)(isq ? qb : pb);
        float4 bb = bias4[s];
        tot.x = a0.x + a1.x + a2.x + a3.x + bb.x;
        tot.y = a0.y + a1.y + a2.y + a3.y + bb.y;
        tot.z = a0.z + a1.z + a2.z + a3.z + bb.z;
        tot.w = a0.w + a1.w + a2.w + a3.w + bb.w;
        partial = tot.x + tot.y + tot.z + tot.w;
    }
    float mean = blockReduceSum(partial, sred) * (1.0f / 1024.0f);

    float4 d = make_float4(tot.x - mean, tot.y - mean, tot.z - mean, tot.w - mean);
    float sq = (active && qd == 0) ? (d.x*d.x + d.y*d.y + d.z*d.z + d.w*d.w) : 0.f;
    float var = blockReduceSum(sq, sred) * (1.0f / 1024.0f);

    if (active && qd == 0) {
        int r = b & 15;
        float rstd = rsqrtf(var + 1e-5f);
        const float4* g4 = (const float4*)(isq ? qg : pg);
        const float4* B4 = (const float4*)(isq ? qB : pB);
        float4 gg = g4[s], BB = B4[s], x;
        x.x = d.x * rstd * gg.x + BB.x;
        x.y = d.y * rstd * gg.y + BB.y;
        x.z = d.z * rstd * gg.z + BB.z;
        x.w = d.w * rstd * gg.w + BB.w;
        float4 o;
        o.x = x.x / (1.f + expf(-x.x));
        o.y = x.y / (1.f + expf(-x.y));
        o.z = x.z / (1.f + expf(-x.z));
        o.w = x.w / (1.f + expf(-x.w));
        ((float4*)(isq ? outq : outp))[r * 256 + s] = o;
    }
}

// ---------------------------------------------------------------------------
// Phase: logits reduce + unimix softmax + gumbel-max sample.
// ---------------------------------------------------------------------------
__device__ void phase_sample(bool doq, bool dop, int t, int tp,
                             const float* qbo, const float* pbo,
                             const float* gprior, const float* gpost,
                             float* out)
{
    int b = blockIdx.x;
    if (b >= 32) return;
    bool isq = b < 16;
    if (isq ? !doq : !dop) return;
    int r = b & 15;
    int s = threadIdx.x >> 5, lane = threadIdx.x & 31;
    int col = s * 32 + lane;

    const float* part = isq ? g_partQ : g_partP;
    float logit = (isq ? qbo : pbo)[col];
#pragma unroll 8
    for (int ch = 0; ch < CH_L; ch++)
        logit += part[(size_t)(ch * 16 + r) * 1024 + col];

    float mx = logit;
#pragma unroll
    for (int o = 16; o; o >>= 1) mx = fmaxf(mx, __shfl_xor_sync(0xffffffffu, mx, o));
    float e = expf(logit - mx);
    float se = e;
#pragma unroll
    for (int o = 16; o; o >>= 1) se += __shfl_xor_sync(0xffffffffu, se, o);
    float p = 0.99f * (e / se) + (0.01f / 32.0f);

    int tt = isq ? t : tp;
    const float* gum = isq ? gprior : gpost;
    float score = logf(p) + gum[(size_t)((tt * 16 + r) * 32 + s) * 32 + lane];

    float bs = score; int bi = lane;
#pragma unroll
    for (int o = 16; o; o >>= 1) {
        float os = __shfl_xor_sync(0xffffffffu, bs, o);
        int   oi = __shfl_xor_sync(0xffffffffu, bi, o);
        if (os > bs || (os == bs && oi < bi)) { bs = os; bi = oi; }
    }

    if (isq) {
        out[((size_t)r * 64 + t) * 5120 + 4096 + col] = (lane == bi) ? 1.0f : 0.0f;
    } else if (lane == bi) {
        g_idx[r * 32 + s] = bi;
    }
}

// ---------------------------------------------------------------------------
// Phase: GRU input (one-hot gather + action + LN + SiLU). Blocks 0..15.
// ---------------------------------------------------------------------------
__device__ void phase_grux(int t, const float* actions,
                           const float* gW, const float* gb,
                           const float* gg, const float* gB,
                           int* sIdx, float* sAct, float* sred)
{
    int b = blockIdx.x;
    bool active = (b < 16);
    int tid = threadIdx.x;
    float v = 0.f;
    if (active) {
        if (tid < 32) sIdx[tid] = g_idx[b * 32 + tid];
        if (tid >= 32 && tid < 38) sAct[tid - 32] = actions[((size_t)b * 64 + t) * 6 + (tid - 32)];
    }
    __syncthreads();
    if (active) {
        int col = tid;
        v = gb[col];
#pragma unroll
        for (int s = 0; s < 32; s++)
            v += gW[(size_t)(s * 32 + sIdx[s]) * 1024 + col];
#pragma unroll
        for (int j = 0; j < 6; j++)
            v += sAct[j] * gW[(size_t)(1024 + j) * 1024 + col];
    }
    float mean = blockReduceSum(active ? v : 0.f, sred) * (1.0f / 1024.0f);
    float d = v - mean;
    float var = blockReduceSum(active ? d * d : 0.f, sred) * (1.0f / 1024.0f);
    if (active) {
        float rstd = rsqrtf(var + 1e-5f);
        float x = d * rstd * gg[threadIdx.x] + gB[threadIdx.x];
        g_gx[b * 1024 + threadIdx.x] = x / (1.0f + expf(-x));
    }
}

// ---------------------------------------------------------------------------
// Phase: gate, spread across the whole grid. 8-lane chunk split + shfl.
// ---------------------------------------------------------------------------
__device__ void phase_gate(int t, const float* gbz, const float* gbc,
                           float* out)
{
    int gt = blockIdx.x * TPB + threadIdx.x;
    int q8 = gt & 7, slot = gt >> 3;            // 16384 float4 slots
    if (slot >= 16384) return;
    int b = slot >> 10, c4 = slot & 1023;

    const float4* pz4 = (const float4*)g_partZ;
    const float4* pc4 = (const float4*)g_partC;
    float4 zp = make_float4(0.f, 0.f, 0.f, 0.f);
    float4 cp = make_float4(0.f, 0.f, 0.f, 0.f);
#pragma unroll
    for (int ch = q8; ch < CH_ZC; ch += 8) {
        float4 a = pz4[(size_t)(ch * 16 + b) * 1024 + c4];
        float4 c = pc4[(size_t)(ch * 16 + b) * 1024 + c4];
        zp.x += a.x; zp.y += a.y; zp.z += a.z; zp.w += a.w;
        cp.x += c.x; cp.y += c.y; cp.z += c.z; cp.w += c.w;
    }
#pragma unroll
    for (int off = 4; off; off >>= 1) {
        zp.x += __shfl_down_sync(0xffffffffu, zp.x, off);
        zp.y += __shfl_down_sync(0xffffffffu, zp.y, off);
        zp.z += __shfl_down_sync(0xffffffffu, zp.z, off);
        zp.w += __shfl_down_sync(0xffffffffu, zp.w, off);
        cp.x += __shfl_down_sync(0xffffffffu, cp.x, off);
        cp.y += __shfl_down_sync(0xffffffffu, cp.y, off);
        cp.z += __shfl_down_sync(0xffffffffu, cp.z, off);
        cp.w += __shfl_down_sync(0xffffffffu, cp.w, off);
    }
    if (q8 == 0) {
        float4 bz = ((const float4*)gbz)[c4], bc = ((const float4*)gbc)[c4];
        zp.x += bz.x; zp.y += bz.y; zp.z += bz.z; zp.w += bz.w;
        cp.x += bc.x; cp.y += bc.y; cp.z += bc.z; cp.w += bc.w;
        float4* dt4 = (float4*)g_deter;
        float4 dv = dt4[b * 1024 + c4], dn;
        float z, cd;
        z = 1.f / (1.f + expf(-zp.x)); cd = tanhf(cp.x); dn.x = (1.f - z) * dv.x + z * cd;
        z = 1.f / (1.f + expf(-zp.y)); cd = tanhf(cp.y); dn.y = (1.f - z) * dv.y + z * cd;
        z = 1.f / (1.f + expf(-zp.z)); cd = tanhf(cp.z); dn.z = (1.f - z) * dv.z + z * cd;
        z = 1.f / (1.f + expf(-zp.w)); cd = tanhf(cp.w); dn.w = (1.f - z) * dv.w + z * cd;
        dt4[b * 1024 + c4] = dn;
        ((float4*)(out + ((size_t)b * 64 + t) * 5120))[c4] = dn;
    }
}

// ---------------------------------------------------------------------------
__global__ void __launch_bounds__(TPB, 1)
wm_kernel(const float* tokens, const float* actions,
          const float* gpost, const float* gprior,
          const float* pW1, const float* pb1, const float* pg1, const float* pB1,
          const float* pW2, const float* pb2, const float* pg2, const float* pB2,
          const float* pWo, const float* pbo,
          const float* qW1, const float* qb1, const float* qg1, const float* qB1,
          const float* qW2, const float* qb2, const float* qg2, const float* qB2,
          const float* qWo, const float* qbo,
          const float* gW, const float* gb, const float* gg, const float* gB,
          const float* gWz, const float* gbz, const float* gWc, const float* gbc,
          float* out)
{
    __shared__ float4 sStage4[GPB * 64];       // 4 groups x 256 floats
    __shared__ float4 sLN[1024];               // ln combine (16KB)
    __shared__ float  sRed[32];
    __shared__ int    sIdx[32];
    __shared__ float  sAct[6];

    int tid = threadIdx.x;
    int g = tid >> 8, gtid = tid & 255;
    int gid2 = g * NBLK + blockIdx.x;
    float* sMy = (float*)(sStage4 + g * 64);
    int barId = g + 1;

    const float4* pW1v = (const float4*)pW1; const float4* pW2v = (const float4*)pW2;
    const float4* pWov = (const float4*)pWo;
    const float4* qW1v = (const float4*)qW1; const float4* qW2v = (const float4*)qW2;
    const float4* qWov = (const float4*)qWo;
    const float4* gWzv = (const float4*)gWz; const float4* gWcv = (const float4*)gWc;

    {
        int i = blockIdx.x * TPB + tid;
        if (i < 16 * 4096) g_deter[i] = 0.0f;
    }
    gbar();

    // prologue: posterior(t=0)
    phase_g1(false, true, 0, tokens, qW1v, pW1v, sMy, gtid, gid2, barId);      gbar();
    phase_ln(false, true, qb1, qg1, qB1, pb1, pg1, pB1, CH_Q1, CH_P1,
             g_hqA, g_hpA, sLN, sRed);                                         gbar();
    phase_g23(false, true, qW2v, pW2v, g_hqA, g_hpA, sMy, gtid, gid2, barId);  gbar();
    phase_ln(false, true, qb2, qg2, qB2, pb2, pg2, pB2, CH_L, CH_L,
             g_hqB, g_hpB, sLN, sRed);                                         gbar();
    phase_g23(false, true, qWov, pWov, g_hqB, g_hpB, sMy, gtid, gid2, barId);  gbar();
    phase_sample(false, true, 0, 0, qbo, pbo, gprior, gpost, out);             gbar();

    for (int t = 0; t < 64; t++) {
        phase_grux(t, actions, gW, gb, gg, gB, sIdx, sAct, sRed);              gbar();
        phase_zc(gWzv, gWcv, sMy, gtid, gid2, barId);                          gbar();
        phase_gate(t, gbz, gbc, out);                                          gbar();

        bool dop = (t < 63);
        phase_g1(true, dop, t + 1, tokens, qW1v, pW1v, sMy, gtid, gid2, barId); gbar();
        phase_ln(true, dop, qb1, qg1, qB1, pb1, pg1, pB1, CH_Q1, CH_P1,
                 g_hqA, g_hpA, sLN, sRed);                                      gbar();
        phase_g23(true, dop, qW2v, pW2v, g_hqA, g_hpA, sMy, gtid, gid2, barId); gbar();
        phase_ln(true, dop, qb2, qg2, qB2, pb2, pg2, pB2, CH_L, CH_L,
                 g_hqB, g_hpB, sLN, sRed);                                      gbar();
        phase_g23(true, dop, qWov, pWov, g_hqB, g_hpB, sMy, gtid, gid2, barId); gbar();
        phase_sample(true, dop, t, t + 1, qbo, pbo, gprior, gpost, out);        gbar();
    }
}

// ---------------------------------------------------------------------------
extern "C" void kernel_launch(void* const* d_in, const int* in_sizes, int n_in,
                              void* d_out, int out_size) {
    const float* tokens  = (const float*)d_in[0];
    const float* actions = (const float*)d_in[1];
    const float* gpost   = (const float*)d_in[2];
    const float* gprior  = (const float*)d_in[3];
    const float* pW1 = (const float*)d_in[4];  const float* pb1 = (const float*)d_in[5];
    const float* pg1 = (const float*)d_in[6];  const float* pB1 = (const float*)d_in[7];
    const float* pW2 = (const float*)d_in[8];  const float* pb2 = (const float*)d_in[9];
    const float* pg2 = (const float*)d_in[10]; const float* pB2 = (const float*)d_in[11];
    const float* pWo = (const float*)d_in[12]; const float* pbo = (const float*)d_in[13];
    const float* qW1 = (const float*)d_in[14]; const float* qb1 = (const float*)d_in[15];
    const float* qg1 = (const float*)d_in[16]; const float* qB1 = (const float*)d_in[17];
    const float* qW2 = (const float*)d_in[18]; const float* qb2 = (const float*)d_in[19];
    const float* qg2 = (const float*)d_in[20]; const float* qB2 = (const float*)d_in[21];
    const float* qWo = (const float*)d_in[22]; const float* qbo = (const float*)d_in[23];
    const float* gW  = (const float*)d_in[24]; const float* gb  = (const float*)d_in[25];
    const float* gg  = (const float*)d_in[26]; const float* gB  = (const float*)d_in[27];
    const float* gWz = (const float*)d_in[28]; const float* gbz = (const float*)d_in[29];
    const float* gWc = (const float*)d_in[30]; const float* gbc = (const float*)d_in[31];

    wm_kernel<<<NBLK, TPB>>>(tokens, actions, gpost, gprior,
                             pW1, pb1, pg1, pB1, pW2, pb2, pg2, pB2, pWo, pbo,
                             qW1, qb1, qg1, qB1, qW2, qb2, qg2, qB2, qWo, qbo,
                             gW, gb, gg, gB, gWz, gbz, gWc, gbc,
                             (float*)d_out);
}

// round 11
// speedup vs baseline: 1.1228x; 1.0385x over previous
#include <cuda_runtime.h>
#include <cstddef>

// ===========================================================================
// WorldModel RSSM persistent kernel, barrier-free GEMM inner loops.
// S=32 C=32 D=4096 H=1024 A=6 B=16 T=64 TOK=4096, out feats [16,64,5120]
// ===========================================================================

#define NBLK 148
#define TPB  1024
#define GPB  4                  // 256-thread groups per block
#define NG   (NBLK * GPB)       // 592 groups

#define CH_Q1 64                // prior layer1:  K=4096, Kc=64
#define CH_P1 128               // post  layer1:  K=8192, Kc=64
#define CH_L  32                // layers 2/3:    K=1024, Kc=32
#define CH_ZC 32                // z/cand:        K=5120, Kc=160

// ---------------------------------------------------------------------------
// Device scratch
// ---------------------------------------------------------------------------
__device__ float g_deter[16 * 4096];
__device__ float g_gx[16 * 1024];
__device__ float g_hqA[16 * 1024];
__device__ float g_hqB[16 * 1024];
__device__ float g_hpA[16 * 1024];
__device__ float g_hpB[16 * 1024];
__device__ float g_partQ[CH_Q1 * 16 * 1024];
__device__ float g_partP[CH_P1 * 16 * 1024];
__device__ float g_partZ[CH_ZC * 16 * 4096];
__device__ float g_partC[CH_ZC * 16 * 4096];
__device__ unsigned g_count;
__device__ unsigned g_gen;

// ---------------------------------------------------------------------------
__device__ __forceinline__ float2 ffma2(float2 a, float2 b, float2 c) {
    union U { float2 f; unsigned long long u; };
    U ua, ub, uc, ud;
    ua.f = a; ub.f = b; uc.f = c;
    asm("fma.rn.f32x2 %0, %1, %2, %3;"
        : "=l"(ud.u) : "l"(ua.u), "l"(ub.u), "l"(uc.u));
    return ud.f;
}

__device__ __forceinline__ void gbar() {
    __syncthreads();
    if (threadIdx.x == 0) {
        volatile unsigned* vg = &g_gen;
        unsigned gen = *vg;
        __threadfence();
        if (atomicAdd(&g_count, 1u) == NBLK - 1) {
            g_count = 0;
            __threadfence();
            *vg = gen + 1;
        } else {
            while (*vg == gen) { __nanosleep(32); }
        }
        __threadfence();
    }
    __syncthreads();
}

__device__ __forceinline__ float blockReduceSum(float v, float* sred) {
    int lane = threadIdx.x & 31, wid = threadIdx.x >> 5;
#pragma unroll
    for (int o = 16; o; o >>= 1) v += __shfl_xor_sync(0xffffffffu, v, o);
    __syncthreads();
    if (lane == 0) sred[wid] = v;
    __syncthreads();
    if (wid == 0) {
        float t = sred[lane];
#pragma unroll
        for (int o = 16; o; o >>= 1) t += __shfl_xor_sync(0xffffffffu, t, o);
        if (lane == 0) sred[0] = t;
    }
    __syncthreads();
    return sred[0];
}

struct InDesc { const float* A; int strideA; int offA; int KA; const float* B; };

// ---------------------------------------------------------------------------
// GEMM tile, R rows per thread (8 or 4), 4 cols per thread (LDG.128).
// Group = 256 threads covering 1024 columns. Full A chunk staged to smem
// once; the kk loop is barrier-free so weight-load latency pipelines.
// ---------------------------------------------------------------------------
template <int R>
__device__ __forceinline__ void gemm_g(
    InDesc in, const float4* __restrict__ W4, int N4,
    int c4base, int rowbase, int k0, int Kc,
    float4* __restrict__ part4, int chunkIdx,
    float* sA, int gtid, int barId)
{
    // stage A[rowbase..rowbase+R-1][k0..k0+Kc-1] -> sA[k*R + r]
    for (int idx = gtid; idx < R * Kc; idx += 256) {
        int r = idx / Kc, k = idx - r * Kc;
        int row = rowbase + r, gk = k0 + k;
        float v = (gk < in.KA) ? in.A[(size_t)row * in.strideA + in.offA + gk]
                               : in.B[(size_t)row * 4096 + (gk - in.KA)];
        sA[k * R + r] = v;
    }
    asm volatile("bar.sync %0, %1;" :: "r"(barId), "r"(256) : "memory");

    float2 acc[R / 2][4];
#pragma unroll
    for (int rp = 0; rp < R / 2; rp++)
#pragma unroll
        for (int c = 0; c < 4; c++) acc[rp][c] = make_float2(0.f, 0.f);

    const float4* Wp = W4 + (size_t)k0 * N4 + (c4base + gtid);
    const float4* Ap = (const float4*)sA;

#pragma unroll 4
    for (int kk = 0; kk < Kc; kk++) {
        float4 w = Wp[0]; Wp += N4;
        float2 wx = make_float2(w.x, w.x), wy = make_float2(w.y, w.y);
        float2 wz = make_float2(w.z, w.z), ww = make_float2(w.w, w.w);
        if (R == 8) {
            float4 a0 = Ap[0], a1 = Ap[1]; Ap += 2;
            float2 p0 = make_float2(a0.x, a0.y), p1 = make_float2(a0.z, a0.w);
            float2 p2 = make_float2(a1.x, a1.y), p3 = make_float2(a1.z, a1.w);
            acc[0][0] = ffma2(p0, wx, acc[0][0]); acc[0][1] = ffma2(p0, wy, acc[0][1]);
            acc[0][2] = ffma2(p0, wz, acc[0][2]); acc[0][3] = ffma2(p0, ww, acc[0][3]);
            acc[1][0] = ffma2(p1, wx, acc[1][0]); acc[1][1] = ffma2(p1, wy, acc[1][1]);
            acc[1][2] = ffma2(p1, wz, acc[1][2]); acc[1][3] = ffma2(p1, ww, acc[1][3]);
            acc[2][0] = ffma2(p2, wx, acc[2][0]); acc[2][1] = ffma2(p2, wy, acc[2][1]);
            acc[2][2] = ffma2(p2, wz, acc[2][2]); acc[2][3] = ffma2(p2, ww, acc[2][3]);
            acc[3][0] = ffma2(p3, wx, acc[3][0]); acc[3][1] = ffma2(p3, wy, acc[3][1]);
            acc[3][2] = ffma2(p3, wz, acc[3][2]); acc[3][3] = ffma2(p3, ww, acc[3][3]);
        } else {
            float4 a0 = Ap[0]; Ap += 1;
            float2 p0 = make_float2(a0.x, a0.y), p1 = make_float2(a0.z, a0.w);
            acc[0][0] = ffma2(p0, wx, acc[0][0]); acc[0][1] = ffma2(p0, wy, acc[0][1]);
            acc[0][2] = ffma2(p0, wz, acc[0][2]); acc[0][3] = ffma2(p0, ww, acc[0][3]);
            acc[1][0] = ffma2(p1, wx, acc[1][0]); acc[1][1] = ffma2(p1, wy, acc[1][1]);
            acc[1][2] = ffma2(p1, wz, acc[1][2]); acc[1][3] = ffma2(p1, ww, acc[1][3]);
        }
    }
    asm volatile("bar.sync %0, %1;" :: "r"(barId), "r"(256) : "memory");

#pragma unroll
    for (int r = 0; r < R; r++) {
        int rp = r >> 1;
        float4 o;
        if (r & 1) o = make_float4(acc[rp][0].y, acc[rp][1].y, acc[rp][2].y, acc[rp][3].y);
        else       o = make_float4(acc[rp][0].x, acc[rp][1].x, acc[rp][2].x, acc[rp][3].x);
        part4[(size_t)(chunkIdx * 16 + rowbase + r) * N4 + (c4base + gtid)] = o;
    }
}

// ---------------------------------------------------------------------------
// Phase: fused layer-1 GEMMs. q: deter@qW1 (K=4096). p: [tok(tp),deter]@pW1.
// ---------------------------------------------------------------------------
__device__ void phase_g1(bool doq, bool dop, int tp, const float* tokens,
                         const float4* qW1, const float4* pW1,
                         float* sMy, int gtid, int gid2, int barId)
{
    int qT = doq ? (2 * CH_Q1) : 0;
    int total = qT + (dop ? (2 * CH_P1) : 0);
    for (int t = gid2; t < total; t += NG) {
        if (t < qT) {
            int ch = t >> 1, rh = t & 1;
            InDesc in = { g_deter, 4096, 0, 4096, g_deter };
            gemm_g<8>(in, qW1, 256, 0, rh * 8, ch * 64, 64,
                      (float4*)g_partQ, ch, sMy, gtid, barId);
        } else {
            int u = t - qT;
            int ch = u >> 1, rh = u & 1;
            InDesc in = { tokens, 64 * 4096, tp * 4096, 4096, g_deter };
            gemm_g<8>(in, pW1, 256, 0, rh * 8, ch * 64, 64,
                      (float4*)g_partP, ch, sMy, gtid, barId);
        }
    }
}

// ---------------------------------------------------------------------------
// Phase: fused layer-2/3 GEMMs (K=1024).
// ---------------------------------------------------------------------------
__device__ void phase_g23(bool doq, bool dop,
                          const float4* Wq, const float4* Wp,
                          const float* inq, const float* inp,
                          float* sMy, int gtid, int gid2, int barId)
{
    int qT = doq ? (4 * CH_L) : 0;
    int total = qT + (dop ? (4 * CH_L) : 0);
    for (int t = gid2; t < total; t += NG) {
        bool isq = t < qT;
        int u = isq ? t : (t - qT);
        int ch = u >> 2, rh = u & 3;
        InDesc in = { isq ? inq : inp, 1024, 0, 1024, isq ? inq : inp };
        gemm_g<4>(in, isq ? Wq : Wp, 256, 0, rh * 4, ch * 32, 32,
                  (float4*)(isq ? g_partQ : g_partP), ch, sMy, gtid, barId);
    }
}

// ---------------------------------------------------------------------------
// Phase: z/cand GEMM. in = [gx, deter] (K=5120), N=4096 each. 512 tiles.
// ---------------------------------------------------------------------------
__device__ void phase_zc(const float4* Wz, const float4* Wc,
                         float* sMy, int gtid, int gid2, int barId)
{
    const int total = 2 * 8 * CH_ZC;            // 512
    for (int t = gid2; t < total; t += NG) {
        bool isZ = t < 256;
        int u = t & 255;
        int ch = u >> 3, sub = u & 7;
        int ct = sub >> 1, rh = sub & 1;
        InDesc in = { g_gx, 1024, 0, 1024, g_deter };
        gemm_g<8>(in, isZ ? Wz : Wc, 1024, ct * 256, rh * 8, ch * 160, 160,
                  (float4*)(isZ ? g_partZ : g_partC), ch, sMy, gtid, barId);
    }
}

// ---------------------------------------------------------------------------
// Phase: reduce partials + bias + LN + SiLU. Blocks 0..15 q, 16..31 p.
// ---------------------------------------------------------------------------
__device__ void phase_ln(bool doq, bool dop,
                         const float* qb, const float* qg, const float* qB,
                         const float* pb, const float* pg, const float* pB,
                         int chq, int chp, float* outq, float* outp,
                         float4* sLN, float* sred)
{
    int b = blockIdx.x;
    bool active = (b < 32);
    bool isq = b < 16;
    if (active && (isq ? !doq : !dop)) active = false;

    int s = threadIdx.x & 255, qd = threadIdx.x >> 8;
    float4 v = make_float4(0.f, 0.f, 0.f, 0.f);
    if (active) {
        int r = b & 15;
        const float4* part4 = (const float4*)(isq ? g_partQ : g_partP);
        int chunks = isq ? chq : chp;
        for (int ch = qd; ch < chunks; ch += 4) {
            float4 a = part4[(size_t)(ch * 16 + r) * 256 + s];
            v.x += a.x; v.y += a.y; v.z += a.z; v.w += a.w;
        }
    }
    sLN[qd * 256 + s] = v;
    __syncthreads();

    float4 tot = make_float4(0.f, 0.f, 0.f, 0.f);
    float partial = 0.f;
    if (active && qd == 0) {
        float4 a0 = sLN[s], a1 = sLN[256 + s], a2 = sLN[512 + s], a3 = sLN[768 + s];
        const float4* bias4 = (const float4*)(isq ? qb : pb);
        float4 bb = bias4[s];
        tot.x = a0.x + a1.x + a2.x + a3.x + bb.x;
        tot.y = a0.y + a1.y + a2.y + a3.y + bb.y;
        tot.z = a0.z + a1.z + a2.z + a3.z + bb.z;
        tot.w = a0.w + a1.w + a2.w + a3.w + bb.w;
        partial = tot.x + tot.y + tot.z + tot.w;
    }
    float mean = blockReduceSum(partial, sred) * (1.0f / 1024.0f);

    float4 d = make_float4(tot.x - mean, tot.y - mean, tot.z - mean, tot.w - mean);
    float sq = (active && qd == 0) ? (d.x*d.x + d.y*d.y + d.z*d.z + d.w*d.w) : 0.f;
    float var = blockReduceSum(sq, sred) * (1.0f / 1024.0f);

    if (active && qd == 0) {
        int r = b & 15;
        float rstd = rsqrtf(var + 1e-5f);
        const float4* g4 = (const float4*)(isq ? qg : pg);
        const float4* B4 = (const float4*)(isq ? qB : pB);
        float4 gg = g4[s], BB = B4[s], x;
        x.x = d.x * rstd * gg.x + BB.x;
        x.y = d.y * rstd * gg.y + BB.y;
        x.z = d.z * rstd * gg.z + BB.z;
        x.w = d.w * rstd * gg.w + BB.w;
        float4 o;
        o.x = x.x / (1.f + expf(-x.x));
        o.y = x.y / (1.f + expf(-x.y));
        o.z = x.z / (1.f + expf(-x.z));
        o.w = x.w / (1.f + expf(-x.w));
        ((float4*)(isq ? outq : outp))[r * 256 + s] = o;
    }
}

// ---------------------------------------------------------------------------
// Merged phase: sample (prior t -> out, posterior tp -> smem idx) then
// GRU-input for step tp in the same block (no extra grid barrier).
// Blocks 0..15: prior sample, batch b.  Blocks 16..31: posterior + grux.
// ---------------------------------------------------------------------------
__device__ void phase_sample_grux(bool doq, bool dop, int t, int tp,
                                  const float* qbo, const float* pbo,
                                  const float* gprior, const float* gpost,
                                  const float* actions,
                                  const float* gW, const float* gb,
                                  const float* gg, const float* gB,
                                  int* sIdx, float* sAct, float* sred,
                                  float* out)
{
    int b = blockIdx.x;
    bool isq = b < 16;
    bool samp = (b < 32) && (isq ? doq : dop);
    bool grux = (b >= 16) && (b < 32) && dop;
    int r = b & 15;
    int s = threadIdx.x >> 5, lane = threadIdx.x & 31;

    if (grux && threadIdx.x < 6)
        sAct[threadIdx.x] = actions[((size_t)r * 64 + tp) * 6 + threadIdx.x];

    if (samp) {
        int col = s * 32 + lane;
        const float* part = isq ? g_partQ : g_partP;
        float logit = (isq ? qbo : pbo)[col];
#pragma unroll 8
        for (int ch = 0; ch < CH_L; ch++)
            logit += part[(size_t)(ch * 16 + r) * 1024 + col];

        float mx = logit;
#pragma unroll
        for (int o = 16; o; o >>= 1) mx = fmaxf(mx, __shfl_xor_sync(0xffffffffu, mx, o));
        float e = expf(logit - mx);
        float se = e;
#pragma unroll
        for (int o = 16; o; o >>= 1) se += __shfl_xor_sync(0xffffffffu, se, o);
        float p = 0.99f * (e / se) + (0.01f / 32.0f);

        int tt = isq ? t : tp;
        const float* gum = isq ? gprior : gpost;
        float score = logf(p) + gum[(size_t)((tt * 16 + r) * 32 + s) * 32 + lane];

        float bs = score; int bi = lane;
#pragma unroll
        for (int o = 16; o; o >>= 1) {
            float os = __shfl_xor_sync(0xffffffffu, bs, o);
            int   oi = __shfl_xor_sync(0xffffffffu, bi, o);
            if (os > bs || (os == bs && oi < bi)) { bs = os; bi = oi; }
        }
        if (isq) {
            out[((size_t)r * 64 + t) * 5120 + 4096 + col] = (lane == bi) ? 1.0f : 0.0f;
        } else if (lane == bi) {
            sIdx[s] = bi;
        }
    }
    __syncthreads();

    float v = 0.f;
    if (grux) {
        int col = threadIdx.x;
        v = gb[col];
#pragma unroll
        for (int s2 = 0; s2 < 32; s2++)
            v += gW[(size_t)(s2 * 32 + sIdx[s2]) * 1024 + col];
#pragma unroll
        for (int j = 0; j < 6; j++)
            v += sAct[j] * gW[(size_t)(1024 + j) * 1024 + col];
    }
    float mean = blockReduceSum(grux ? v : 0.f, sred) * (1.0f / 1024.0f);
    float d = v - mean;
    float var = blockReduceSum(grux ? d * d : 0.f, sred) * (1.0f / 1024.0f);
    if (grux) {
        float rstd = rsqrtf(var + 1e-5f);
        float x = d * rstd * gg[threadIdx.x] + gB[threadIdx.x];
        g_gx[r * 1024 + threadIdx.x] = x / (1.0f + expf(-x));
    }
}

// ---------------------------------------------------------------------------
// Phase: gate — reduce z/cand partials, update deter, write feats slice.
// ---------------------------------------------------------------------------
__device__ void phase_gate(int t, const float* gbz, const float* gbc,
                           float* out)
{
    int gt = blockIdx.x * TPB + threadIdx.x;
    int q8 = gt & 7, slot = gt >> 3;
    if (slot >= 16384) return;
    int b = slot >> 10, c4 = slot & 1023;

    const float4* pz4 = (const float4*)g_partZ;
    const float4* pc4 = (const float4*)g_partC;
    float4 zp = make_float4(0.f, 0.f, 0.f, 0.f);
    float4 cp = make_float4(0.f, 0.f, 0.f, 0.f);
#pragma unroll
    for (int ch = q8; ch < CH_ZC; ch += 8) {
        float4 a = pz4[(size_t)(ch * 16 + b) * 1024 + c4];
        float4 c = pc4[(size_t)(ch * 16 + b) * 1024 + c4];
        zp.x += a.x; zp.y += a.y; zp.z += a.z; zp.w += a.w;
        cp.x += c.x; cp.y += c.y; cp.z += c.z; cp.w += c.w;
    }
#pragma unroll
    for (int off = 4; off; off >>= 1) {
        zp.x += __shfl_down_sync(0xffffffffu, zp.x, off);
        zp.y += __shfl_down_sync(0xffffffffu, zp.y, off);
        zp.z += __shfl_down_sync(0xffffffffu, zp.z, off);
        zp.w += __shfl_down_sync(0xffffffffu, zp.w, off);
        cp.x += __shfl_down_sync(0xffffffffu, cp.x, off);
        cp.y += __shfl_down_sync(0xffffffffu, cp.y, off);
        cp.z += __shfl_down_sync(0xffffffffu, cp.z, off);
        cp.w += __shfl_down_sync(0xffffffffu, cp.w, off);
    }
    if (q8 == 0) {
        float4 bz = ((const float4*)gbz)[c4], bc = ((const float4*)gbc)[c4];
        zp.x += bz.x; zp.y += bz.y; zp.z += bz.z; zp.w += bz.w;
        cp.x += bc.x; cp.y += bc.y; cp.z += bc.z; cp.w += bc.w;
        float4* dt4 = (float4*)g_deter;
        float4 dv = dt4[b * 1024 + c4], dn;
        float z, cd;
        z = 1.f / (1.f + expf(-zp.x)); cd = tanhf(cp.x); dn.x = (1.f - z) * dv.x + z * cd;
        z = 1.f / (1.f + expf(-zp.y)); cd = tanhf(cp.y); dn.y = (1.f - z) * dv.y + z * cd;
        z = 1.f / (1.f + expf(-zp.z)); cd = tanhf(cp.z); dn.z = (1.f - z) * dv.z + z * cd;
        z = 1.f / (1.f + expf(-zp.w)); cd = tanhf(cp.w); dn.w = (1.f - z) * dv.w + z * cd;
        dt4[b * 1024 + c4] = dn;
        ((float4*)(out + ((size_t)b * 64 + t) * 5120))[c4] = dn;
    }
}

// ---------------------------------------------------------------------------
__global__ void __launch_bounds__(TPB, 1)
wm_kernel(const float* tokens, const float* actions,
          const float* gpost, const float* gprior,
          const float* pW1, const float* pb1, const float* pg1, const float* pB1,
          const float* pW2, const float* pb2, const float* pg2, const float* pB2,
          const float* pWo, const float* pbo,
          const float* qW1, const float* qb1, const float* qg1, const float* qB1,
          const float* qW2, const float* qb2, const float* qg2, const float* qB2,
          const float* qWo, const float* qbo,
          const float* gW, const float* gb, const float* gg, const float* gB,
          const float* gWz, const float* gbz, const float* gWc, const float* gbc,
          float* out)
{
    __shared__ float  sStage[GPB * 160 * 8];   // 4 groups x 5 KB A staging
    __shared__ float4 sLN[1024];
    __shared__ float  sRed[32];
    __shared__ int    sIdx[32];
    __shared__ float  sAct[6];

    int tid = threadIdx.x;
    int g = tid >> 8, gtid = tid & 255;
    int gid2 = g * NBLK + blockIdx.x;
    float* sMy = sStage + g * 160 * 8;
    int barId = g + 1;

    const float4* pW1v = (const float4*)pW1; const float4* pW2v = (const float4*)pW2;
    const float4* pWov = (const float4*)pWo;
    const float4* qW1v = (const float4*)qW1; const float4* qW2v = (const float4*)qW2;
    const float4* qWov = (const float4*)qWo;
    const float4* gWzv = (const float4*)gWz; const float4* gWcv = (const float4*)gWc;

    {
        int i = blockIdx.x * TPB + tid;
        if (i < 16 * 4096) g_deter[i] = 0.0f;
    }
    gbar();

    // prologue: posterior(0) + grux(0)
    phase_g1(false, true, 0, tokens, qW1v, pW1v, sMy, gtid, gid2, barId);      gbar();
    phase_ln(false, true, qb1, qg1, qB1, pb1, pg1, pB1, CH_Q1, CH_P1,
             g_hqA, g_hpA, sLN, sRed);                                         gbar();
    phase_g23(false, true, qW2v, pW2v, g_hqA, g_hpA, sMy, gtid, gid2, barId);  gbar();
    phase_ln(false, true, qb2, qg2, qB2, pb2, pg2, pB2, CH_L, CH_L,
             g_hqB, g_hpB, sLN, sRed);                                         gbar();
    phase_g23(false, true, qWov, pWov, g_hqB, g_hpB, sMy, gtid, gid2, barId);  gbar();
    phase_sample_grux(false, true, 0, 0, qbo, pbo, gprior, gpost,
                      actions, gW, gb, gg, gB, sIdx, sAct, sRed, out);         gbar();

    for (int t = 0; t < 64; t++) {
        phase_zc(gWzv, gWcv, sMy, gtid, gid2, barId);                          gbar();
        phase_gate(t, gbz, gbc, out);                                          gbar();

        bool dop = (t < 63);
        phase_g1(true, dop, t + 1, tokens, qW1v, pW1v, sMy, gtid, gid2, barId); gbar();
        phase_ln(true, dop, qb1, qg1, qB1, pb1, pg1, pB1, CH_Q1, CH_P1,
                 g_hqA, g_hpA, sLN, sRed);                                      gbar();
        phase_g23(true, dop, qW2v, pW2v, g_hqA, g_hpA, sMy, gtid, gid2, barId); gbar();
        phase_ln(true, dop, qb2, qg2, qB2, pb2, pg2, pB2, CH_L, CH_L,
                 g_hqB, g_hpB, sLN, sRed);                                      gbar();
        phase_g23(true, dop, qWov, pWov, g_hqB, g_hpB, sMy, gtid, gid2, barId); gbar();
        phase_sample_grux(true, dop, t, t + 1, qbo, pbo, gprior, gpost,
                          actions, gW, gb, gg, gB, sIdx, sAct, sRed, out);      gbar();
    }
}

// ---------------------------------------------------------------------------
extern "C" void kernel_launch(void* const* d_in, const int* in_sizes, int n_in,
                              void* d_out, int out_size) {
    const float* tokens  = (const float*)d_in[0];
    const float* actions = (const float*)d_in[1];
    const float* gpost   = (const float*)d_in[2];
    const float* gprior  = (const float*)d_in[3];
    const float* pW1 = (const float*)d_in[4];  const float* pb1 = (const float*)d_in[5];
    const float* pg1 = (const float*)d_in[6];  const float* pB1 = (const float*)d_in[7];
    const float* pW2 = (const float*)d_in[8];  const float* pb2 = (const float*)d_in[9];
    const float* pg2 = (const float*)d_in[10]; const float* pB2 = (const float*)d_in[11];
    const float* pWo = (const float*)d_in[12]; const float* pbo = (const float*)d_in[13];
    const float* qW1 = (const float*)d_in[14]; const float* qb1 = (const float*)d_in[15];
    const float* qg1 = (const float*)d_in[16]; const float* qB1 = (const float*)d_in[17];
    const float* qW2 = (const float*)d_in[18]; const float* qb2 = (const float*)d_in[19];
    const float* qg2 = (const float*)d_in[20]; const float* qB2 = (const float*)d_in[21];
    const float* qWo = (const float*)d_in[22]; const float* qbo = (const float*)d_in[23];
    const float* gW  = (const float*)d_in[24]; const float* gb  = (const float*)d_in[25];
    const float* gg  = (const float*)d_in[26]; const float* gB  = (const float*)d_in[27];
    const float* gWz = (const float*)d_in[28]; const float* gbz = (const float*)d_in[29];
    const float* gWc = (const float*)d_in[30]; const float* gbc = (const float*)d_in[31];

    wm_kernel<<<NBLK, TPB>>>(tokens, actions, gpost, gprior,
                             pW1, pb1, pg1, pB1, pW2, pb2, pg2, pB2, pWo, pbo,
                             qW1, qb1, qg1, qB1, qW2, qb2, qg2, qB2, qWo, qbo,
                             gW, gb, gg, gB, gWz, gbz, gWc, gbc,
                             (float*)d_out);
}